// round 8
// baseline (speedup 1.0000x reference)
#include <cuda_runtime.h>
#include <cstdint>
#include <math.h>

// tril(A @ B), A,B lower-triangular fp32, N=4096.
// bf16 3-split GEMM on mma.sync.m16n8k16 (tcgen05/TMA unavailable: harness
// PTX target is sm_103 without 'a').
//
// R8 = R4 geometry (128x128 tile, 256 thr, 64x32 warp tiles, 1 CTA/SM)
//  + term-major MMA ordering (dependent HMMAs 16 apart, not 1 apart)
//  + produce interleaved into compute (LDG before MMAs; cvt+STS of A-half
//    between ks-groups, B-half after; only tail is one __syncthreads).

#define NDIM 4096
#define NB   32
#define BK   32
#define THREADS 256

#define A_ROWB 80              // 32 bf16 = 64B padded to 80B
#define ST_AH 0                // 128*80 = 10240
#define ST_AL 10240
#define ST_BH 20480            // 32 k-rows * 256B = 8192
#define ST_BL 28672
#define STAGE 36864
#define SMEM_DYN (2 * STAGE)   // 73728

static __device__ __forceinline__ uint32_t smem_u32(const void* p) {
    uint32_t a;
    asm("{ .reg .u64 t; cvta.to.shared.u64 t, %1; cvt.u32.u64 %0, t; }"
        : "=r"(a) : "l"(p));
    return a;
}

// pack two fp32 -> bf16x2, 'lo' in bits[15:0], 'hi' in bits[31:16]
static __device__ __forceinline__ uint32_t bf2(float lo, float hi) {
    uint32_t r;
    asm("cvt.rn.bf16x2.f32 %0, %1, %2;" : "=r"(r) : "f"(hi), "f"(lo));
    return r;
}

static __device__ __forceinline__ void ldm4(uint32_t d[4], uint32_t addr) {
    asm volatile("ldmatrix.sync.aligned.m8n8.x4.shared.b16 {%0,%1,%2,%3}, [%4];"
                 : "=r"(d[0]), "=r"(d[1]), "=r"(d[2]), "=r"(d[3]) : "r"(addr));
}
static __device__ __forceinline__ void ldm4t(uint32_t d[4], uint32_t addr) {
    asm volatile("ldmatrix.sync.aligned.m8n8.x4.trans.shared.b16 {%0,%1,%2,%3}, [%4];"
                 : "=r"(d[0]), "=r"(d[1]), "=r"(d[2]), "=r"(d[3]) : "r"(addr));
}

static __device__ __forceinline__ void mma16816(float* c, const uint32_t* a,
                                                const uint32_t* b) {
    asm volatile(
        "mma.sync.aligned.m16n8k16.row.col.f32.bf16.bf16.f32 "
        "{%0,%1,%2,%3}, {%4,%5,%6,%7}, {%8,%9}, {%0,%1,%2,%3};"
        : "+f"(c[0]), "+f"(c[1]), "+f"(c[2]), "+f"(c[3])
        : "r"(a[0]), "r"(a[1]), "r"(a[2]), "r"(a[3]), "r"(b[0]), "r"(b[1]));
}

static __device__ __forceinline__ void split4(float4 v, uint32_t& h01, uint32_t& h23,
                                              uint32_t& l01, uint32_t& l23) {
    h01 = bf2(v.x, v.y);
    h23 = bf2(v.z, v.w);
    float r0 = v.x - __uint_as_float(h01 << 16);
    float r1 = v.y - __uint_as_float(h01 & 0xFFFF0000u);
    float r2 = v.z - __uint_as_float(h23 << 16);
    float r3 = v.w - __uint_as_float(h23 & 0xFFFF0000u);
    l01 = bf2(r0, r1);
    l23 = bf2(r2, r3);
}

static __device__ __forceinline__ void sts4(uint32_t addr, uint32_t a, uint32_t b,
                                            uint32_t c, uint32_t d) {
    asm volatile("st.shared.v4.b32 [%0], {%1,%2,%3,%4};"
                 :: "r"(addr), "r"(a), "r"(b), "r"(c), "r"(d) : "memory");
}

__global__ __launch_bounds__(THREADS, 1)
void trimm_mma(const float* __restrict__ A, const float* __restrict__ B,
               float* __restrict__ C)
{
    extern __shared__ __align__(128) char dyn_smem[];
    const uint32_t sbase = smem_u32(dyn_smem);

    const int tid  = threadIdx.x;
    const int wid  = tid >> 5;
    const int lane = tid & 31;

    // ---- block id -> (bi,bj), largest-K first ----
    int t = blockIdx.x;
    int g = (int)((sqrtf(8.0f * (float)t + 1.0f) - 1.0f) * 0.5f);
    while ((g + 1) * (g + 2) / 2 <= t) ++g;
    while (g * (g + 1) / 2 > t) --g;
    const int bj = t - g * (g + 1) / 2;
    const int bi = bj + (NB - 1) - g;
    const int bm0 = bi * 128, bn0 = bj * 128;
    const int kStart = bn0, kEnd = bm0 + 128;
    const int nchunks = (kEnd - kStart) >> 5;   // 4..128

    // warp grid 2(m) x 4(n): warp tile 64x32
    const int m0w = (wid & 1) * 64;
    const int n0w = (wid >> 1) * 32;

    const uint32_t laneA    = (uint32_t)((lane & 15) * A_ROWB + ((lane >> 4) << 4));
    const uint32_t laneBRow = (uint32_t)((lane & 15) * 256);
    const uint32_t laneBCol = (uint32_t)((((lane >> 4) ^ (lane & 7)) << 4));

    // produce-phase indices: 8 floats/thread per array, v4 stores
    const int aRow = tid >> 2;            // 0..63 (+64 second pass)
    const int aK8  = (tid & 3) * 8;       // k float offset {0,8,16,24}
    const int bK   = tid >> 4;            // 0..15 (+16 second pass)
    const int bN8  = (tid & 15) * 8;      // n float offset {0..120}

    float acc[4][4][4];
#pragma unroll
    for (int mt = 0; mt < 4; ++mt)
#pragma unroll
        for (int nt = 0; nt < 4; ++nt)
#pragma unroll
            for (int e = 0; e < 4; ++e) acc[mt][nt][e] = 0.0f;

    float4 va[4], vb[4];

#define LOAD_REGS(k0)                                                           \
    {                                                                           \
        const float* ap0 = A + (size_t)(bm0 + aRow) * NDIM + (k0) + aK8;        \
        const float* ap1 = A + (size_t)(bm0 + aRow + 64) * NDIM + (k0) + aK8;   \
        const float* bp0 = B + (size_t)((k0) + bK) * NDIM + bn0 + bN8;          \
        const float* bp1 = B + (size_t)((k0) + bK + 16) * NDIM + bn0 + bN8;     \
        va[0] = *(const float4*)ap0;  va[1] = *(const float4*)(ap0 + 4);        \
        va[2] = *(const float4*)ap1;  va[3] = *(const float4*)(ap1 + 4);        \
        vb[0] = *(const float4*)bp0;  vb[1] = *(const float4*)(bp0 + 4);        \
        vb[2] = *(const float4*)bp1;  vb[3] = *(const float4*)(bp1 + 4);        \
    }

#define STORE_A(sbuf)                                                           \
    {                                                                           \
        _Pragma("unroll")                                                       \
        for (int p = 0; p < 2; ++p) {                                           \
            uint32_t h01, h23, l01, l23, h45, h67, l45, l67;                    \
            split4(va[2 * p], h01, h23, l01, l23);                              \
            split4(va[2 * p + 1], h45, h67, l45, l67);                          \
            uint32_t aoff = (uint32_t)((aRow + p * 64) * A_ROWB + aK8 * 2);     \
            sts4((sbuf) + ST_AH + aoff, h01, h23, h45, h67);                    \
            sts4((sbuf) + ST_AL + aoff, l01, l23, l45, l67);                    \
        }                                                                       \
    }

#define STORE_B(sbuf)                                                           \
    {                                                                           \
        _Pragma("unroll")                                                       \
        for (int p = 0; p < 2; ++p) {                                           \
            uint32_t h01, h23, l01, l23, h45, h67, l45, l67;                    \
            split4(vb[2 * p], h01, h23, l01, l23);                              \
            split4(vb[2 * p + 1], h45, h67, l45, l67);                          \
            int kk = bK + p * 16;                                               \
            uint32_t boff = (uint32_t)(kk * 256 +                               \
                            ((bN8 * 2) ^ ((kk & 7) << 4)));                     \
            sts4((sbuf) + ST_BH + boff, h01, h23, h45, h67);                    \
            sts4((sbuf) + ST_BL + boff, l01, l23, l45, l67);                    \
        }                                                                       \
    }

    // one ks-group: load all frags, then term-major MMAs (deps 16 apart)
#define COMPUTE_KS(scur, ks)                                                    \
    {                                                                           \
        uint32_t aH[4][4], aL[4][4], bH[2][4], bL[2][4];                        \
        _Pragma("unroll")                                                       \
        for (int mt = 0; mt < 4; ++mt) {                                        \
            uint32_t ar = (scur) + ST_AH +                                      \
                          (uint32_t)((m0w + 16 * mt) * A_ROWB + (ks) * 2) + laneA; \
            ldm4(aH[mt], ar);                                                   \
            ldm4(aL[mt], ar + (ST_AL - ST_AH));                                 \
        }                                                                       \
        _Pragma("unroll")                                                       \
        for (int ntp = 0; ntp < 2; ++ntp) {                                     \
            uint32_t twoN0 = (uint32_t)((n0w + 16 * ntp) * 2);                  \
            uint32_t br = (scur) + ST_BH + (uint32_t)((ks) * 256) + laneBRow +  \
                          (twoN0 ^ laneBCol);                                   \
            ldm4t(bH[ntp], br);                                                 \
            ldm4t(bL[ntp], br + (ST_BL - ST_BH));                               \
        }                                                                       \
        _Pragma("unroll")                                                       \
        for (int mt = 0; mt < 4; ++mt)                                          \
            _Pragma("unroll")                                                   \
            for (int nt = 0; nt < 4; ++nt)                                      \
                mma16816(acc[mt][nt], aH[mt], &bH[nt >> 1][(nt & 1) * 2]);      \
        _Pragma("unroll")                                                       \
        for (int mt = 0; mt < 4; ++mt)                                          \
            _Pragma("unroll")                                                   \
            for (int nt = 0; nt < 4; ++nt)                                      \
                mma16816(acc[mt][nt], aL[mt], &bH[nt >> 1][(nt & 1) * 2]);      \
        _Pragma("unroll")                                                       \
        for (int mt = 0; mt < 4; ++mt)                                          \
            _Pragma("unroll")                                                   \
            for (int nt = 0; nt < 4; ++nt)                                      \
                mma16816(acc[mt][nt], aH[mt], &bL[nt >> 1][(nt & 1) * 2]);      \
    }

    // prologue: fill stage 0
    LOAD_REGS(kStart);
    STORE_A(sbase);
    STORE_B(sbase);
    __syncthreads();

    for (int c = 0; c < nchunks; ++c) {
        const uint32_t scur = sbase + (uint32_t)(c & 1) * STAGE;
        const uint32_t snxt = sbase + (uint32_t)((c + 1) & 1) * STAGE;
        const bool more = (c + 1 < nchunks);

        if (more) LOAD_REGS(kStart + (c + 1) * BK);

        COMPUTE_KS(scur, 0);
        if (more) STORE_A(snxt);       // overlaps with tensor-pipe drain
        COMPUTE_KS(scur, 16);
        if (more) STORE_B(snxt);

        __syncthreads();
    }

    // ---- epilogue: tril-masked stores ----
#pragma unroll
    for (int mt = 0; mt < 4; ++mt) {
        const int r0 = bm0 + m0w + 16 * mt + (lane >> 2);
#pragma unroll
        for (int nt = 0; nt < 4; ++nt) {
            const int c0 = bn0 + n0w + 8 * nt + 2 * (lane & 3);
            float* p0 = C + (size_t)r0 * NDIM + c0;
            float* p1 = p0 + 8 * (size_t)NDIM;
            if (c0     <= r0)     p0[0] = acc[mt][nt][0];
            if (c0 + 1 <= r0)     p0[1] = acc[mt][nt][1];
            if (c0     <= r0 + 8) p1[0] = acc[mt][nt][2];
            if (c0 + 1 <= r0 + 8) p1[1] = acc[mt][nt][3];
        }
    }
}

extern "C" void kernel_launch(void* const* d_in, const int* in_sizes, int n_in,
                              void* d_out, int out_size) {
    const float* A = (const float*)d_in[0];
    const float* B = (const float*)d_in[1];
    float* C = (float*)d_out;

    cudaFuncSetAttribute(trimm_mma, cudaFuncAttributeMaxDynamicSharedMemorySize,
                         SMEM_DYN);

    // zero output (kernel never writes the strict upper triangle)
    cudaMemsetAsync(C, 0, (size_t)NDIM * NDIM * sizeof(float), 0);

    const int nblocks = NB * (NB + 1) / 2;   // 528
    trimm_mma<<<nblocks, THREADS, SMEM_DYN>>>(A, B, C);
}